// round 7
// baseline (speedup 1.0000x reference)
#include <cuda_runtime.h>
#include <math_constants.h>

#define NN     50000
#define EE     800000
#define PP     3
#define INF_   128
#define HH     8
#define DD     32
#define HD     256
#define EMB    128
#define KTOT   768
#define M_ROWS (PP * NN)
#define NBLK_SCAN ((M_ROWS + 2047) / 2048)

// -------- device scratch --------
__device__ float g_feat[(size_t)PP * NN * HD];
__device__ float g_z   [(size_t)PP * NN * HD];
__device__ float g_el  [M_ROWS * HH];
__device__ float g_er  [M_ROWS * HH];
__device__ int   g_deg [M_ROWS];
__device__ int   g_off [M_ROWS];
__device__ int   g_cur [M_ROWS];
__device__ int   g_bsum[256];
__device__ int   g_csrc[PP * EE];

__device__ __forceinline__ float lrelu(float x) { return x > 0.f ? x : 0.2f * x; }

// -------- CSR build --------
__global__ void k_zero_deg() {
    int i = blockIdx.x * blockDim.x + threadIdx.x;
    if (i < M_ROWS) g_deg[i] = 0;
}

__global__ void k_hist(const int* __restrict__ ei) {
    int id = blockIdx.x * blockDim.x + threadIdx.x;
    if (id >= PP * EE) return;
    int p = id / EE, e = id - p * EE;
    int dst = ei[(size_t)p * 2 * EE + EE + e];
    atomicAdd(&g_deg[p * NN + dst], 1);
}

__global__ void k_scan1() {
    __shared__ int sd[256];
    int b = blockIdx.x, t = threadIdx.x;
    int base = b * 2048 + t * 8;
    int v[8]; int s = 0;
#pragma unroll
    for (int i = 0; i < 8; i++) {
        int x = (base + i < M_ROWS) ? g_deg[base + i] : 0;
        v[i] = s; s += x;
    }
    sd[t] = s; __syncthreads();
    for (int off = 1; off < 256; off <<= 1) {
        int x = (t >= off) ? sd[t - off] : 0;
        __syncthreads();
        sd[t] += x;
        __syncthreads();
    }
    int exc = sd[t] - s;
#pragma unroll
    for (int i = 0; i < 8; i++)
        if (base + i < M_ROWS) g_off[base + i] = exc + v[i];
    if (t == 255) g_bsum[b] = sd[255];
}

__global__ void k_scan23() {
    __shared__ int sb[NBLK_SCAN];
    if (threadIdx.x < NBLK_SCAN) sb[threadIdx.x] = g_bsum[threadIdx.x];
    __syncthreads();
    int i = blockIdx.x * blockDim.x + threadIdx.x;
    if (i >= M_ROWS) return;
    int b = i >> 11;
    int s = 0;
    for (int j = 0; j < b; j++) s += sb[j];
    int o = g_off[i] + s;
    g_off[i] = o;
    g_cur[i] = o;
}

__global__ void k_scatter(const int* __restrict__ ei) {
    int id = blockIdx.x * blockDim.x + threadIdx.x;
    if (id >= PP * EE) return;
    int p = id / EE, e = id - p * EE;
    int src = ei[(size_t)p * 2 * EE + e];
    int dst = ei[(size_t)p * 2 * EE + EE + e];
    int pos = atomicAdd(&g_cur[p * NN + dst], 1);
    g_csrc[pos] = src;
}

// -------- K1: feat = h @ fc_w, fused el/er. 128x128 tile, 8x8 micro, double-buffered --------
__global__ void __launch_bounds__(256, 2)
k_gemm_feat(const float* __restrict__ hmat, const float* __restrict__ fw,
            const float* __restrict__ al, const float* __restrict__ ar) {
    const int p  = blockIdx.z;
    const int m0 = blockIdx.x * 128;
    const int n0 = blockIdx.y * 128;
    const float* W = fw + (size_t)p * INF_ * HD;

    __shared__ float As[2][16][132];
    __shared__ float Bs[2][16][128];

    const int tid = threadIdx.x;
    const int tx  = tid & 15;
    const int ty  = tid >> 4;

    // staging geometry (per chunk: A 128x16, B 16x128; 2 float4 each per thread)
    const int rowA = tid >> 2;            // 0..63; second A load at rowA+64
    const int kgA  = (tid & 3) * 4;
    const int kB   = tid >> 5;            // 0..7;  second B load at kB+8
    const int nB   = (tid & 31) * 4;

    float4 ra0, ra1, rb0, rb1;
    float acc[8][8] = {};

    float alv[8], arv[8];
#pragma unroll
    for (int j = 0; j < 8; j++) {
        alv[j] = al[p * HD + n0 + tx * 8 + j];
        arv[j] = ar[p * HD + n0 + tx * 8 + j];
    }

    const float4 f4z = make_float4(0.f, 0.f, 0.f, 0.f);

    // preload chunk 0
    {
        int gr0 = m0 + rowA, gr1 = m0 + rowA + 64;
        ra0 = (gr0 < NN) ? *(const float4*)&hmat[(size_t)gr0 * INF_ + kgA] : f4z;
        ra1 = (gr1 < NN) ? *(const float4*)&hmat[(size_t)gr1 * INF_ + kgA] : f4z;
        rb0 = *(const float4*)&W[(size_t)kB * HD + n0 + nB];
        rb1 = *(const float4*)&W[(size_t)(kB + 8) * HD + n0 + nB];
        As[0][kgA + 0][rowA] = ra0.x; As[0][kgA + 1][rowA] = ra0.y;
        As[0][kgA + 2][rowA] = ra0.z; As[0][kgA + 3][rowA] = ra0.w;
        As[0][kgA + 0][rowA + 64] = ra1.x; As[0][kgA + 1][rowA + 64] = ra1.y;
        As[0][kgA + 2][rowA + 64] = ra1.z; As[0][kgA + 3][rowA + 64] = ra1.w;
        *(float4*)&Bs[0][kB][nB]     = rb0;
        *(float4*)&Bs[0][kB + 8][nB] = rb1;
    }
    __syncthreads();

#pragma unroll
    for (int it = 0; it < 8; it++) {
        const int cur = it & 1;
        if (it < 7) {                         // issue next chunk's global loads
            int kc  = (it + 1) * 16;
            int gr0 = m0 + rowA, gr1 = m0 + rowA + 64;
            ra0 = (gr0 < NN) ? *(const float4*)&hmat[(size_t)gr0 * INF_ + kc + kgA] : f4z;
            ra1 = (gr1 < NN) ? *(const float4*)&hmat[(size_t)gr1 * INF_ + kc + kgA] : f4z;
            rb0 = *(const float4*)&W[(size_t)(kc + kB) * HD + n0 + nB];
            rb1 = *(const float4*)&W[(size_t)(kc + kB + 8) * HD + n0 + nB];
        }
        float (*A)[132] = As[cur];
        float (*B)[128] = Bs[cur];
#pragma unroll
        for (int k = 0; k < 16; k++) {
            float4 a0 = *(float4*)&A[k][ty * 8];
            float4 a1 = *(float4*)&A[k][ty * 8 + 4];
            float4 b0 = *(float4*)&B[k][tx * 8];
            float4 b1 = *(float4*)&B[k][tx * 8 + 4];
            float a[8] = {a0.x, a0.y, a0.z, a0.w, a1.x, a1.y, a1.z, a1.w};
            float b[8] = {b0.x, b0.y, b0.z, b0.w, b1.x, b1.y, b1.z, b1.w};
#pragma unroll
            for (int i = 0; i < 8; i++)
#pragma unroll
                for (int j = 0; j < 8; j++) acc[i][j] += a[i] * b[j];
        }
        if (it < 7) {
            const int nxt = cur ^ 1;
            As[nxt][kgA + 0][rowA] = ra0.x; As[nxt][kgA + 1][rowA] = ra0.y;
            As[nxt][kgA + 2][rowA] = ra0.z; As[nxt][kgA + 3][rowA] = ra0.w;
            As[nxt][kgA + 0][rowA + 64] = ra1.x; As[nxt][kgA + 1][rowA + 64] = ra1.y;
            As[nxt][kgA + 2][rowA + 64] = ra1.z; As[nxt][kgA + 3][rowA + 64] = ra1.w;
            *(float4*)&Bs[nxt][kB][nB]     = rb0;
            *(float4*)&Bs[nxt][kB + 8][nB] = rb1;
        }
        __syncthreads();
    }

    const int h = (n0 >> 5) + (tx >> 2);
#pragma unroll
    for (int i = 0; i < 8; i++) {
        int row = m0 + ty * 8 + i;
        if (row < NN) {
            float4 v0 = make_float4(acc[i][0], acc[i][1], acc[i][2], acc[i][3]);
            float4 v1 = make_float4(acc[i][4], acc[i][5], acc[i][6], acc[i][7]);
            float* fp = &g_feat[((size_t)p * NN + row) * HD + n0 + tx * 8];
            *(float4*)fp       = v0;
            *(float4*)(fp + 4) = v1;
        }
        float pel = 0.f, per = 0.f;
#pragma unroll
        for (int j = 0; j < 8; j++) {
            pel += acc[i][j] * alv[j];
            per += acc[i][j] * arv[j];
        }
        pel += __shfl_xor_sync(0xffffffffu, pel, 1);
        pel += __shfl_xor_sync(0xffffffffu, pel, 2);
        per += __shfl_xor_sync(0xffffffffu, per, 1);
        per += __shfl_xor_sync(0xffffffffu, per, 2);
        if ((tx & 3) == 0 && row < NN) {
            g_el[(p * NN + row) * HH + h] = pel;
            g_er[(p * NN + row) * HH + h] = per;
        }
    }
}

// -------- K3: single-pass softmax + aggregate + ELU, warp per (p,dst), unroll 2 --------
__global__ void k_gather() {
    int w    = (int)((blockIdx.x * (size_t)blockDim.x + threadIdx.x) >> 5);
    int lane = threadIdx.x & 31;
    if (w >= M_ROWS) return;
    int p   = w / NN;
    int beg = g_off[w];
    int end = beg + g_deg[w];

    float er_h = (lane < HH) ? g_er[w * HH + lane] : 0.f;

    float4 acc0 = make_float4(0.f, 0.f, 0.f, 0.f);
    float4 acc1 = make_float4(0.f, 0.f, 0.f, 0.f);
    float  den  = 0.f;
    const int hsel = lane >> 3;

    int i = beg;
    for (; i + 2 <= end; i += 2) {
        int s0 = g_csrc[i];
        int s1 = g_csrc[i + 1];
        const float4* f0 = (const float4*)&g_feat[(size_t)(p * NN + s0) * HD];
        const float4* f1 = (const float4*)&g_feat[(size_t)(p * NN + s1) * HD];
        float ex0 = 0.f, ex1 = 0.f;
        if (lane < HH) {
            float el0 = g_el[(p * NN + s0) * HH + lane];
            float el1 = g_el[(p * NN + s1) * HH + lane];
            ex0 = __expf(lrelu(el0 + er_h));
            ex1 = __expf(lrelu(el1 + er_h));
            den += ex0 + ex1;
        }
        float4 u0 = f0[lane];
        float4 u1 = f0[32 + lane];
        float4 v0 = f1[lane];
        float4 v1 = f1[32 + lane];
        float e00 = __shfl_sync(0xffffffffu, ex0, hsel);
        float e01 = __shfl_sync(0xffffffffu, ex0, 4 + hsel);
        float e10 = __shfl_sync(0xffffffffu, ex1, hsel);
        float e11 = __shfl_sync(0xffffffffu, ex1, 4 + hsel);
        acc0.x += u0.x * e00 + v0.x * e10;
        acc0.y += u0.y * e00 + v0.y * e10;
        acc0.z += u0.z * e00 + v0.z * e10;
        acc0.w += u0.w * e00 + v0.w * e10;
        acc1.x += u1.x * e01 + v1.x * e11;
        acc1.y += u1.y * e01 + v1.y * e11;
        acc1.z += u1.z * e01 + v1.z * e11;
        acc1.w += u1.w * e01 + v1.w * e11;
    }
    for (; i < end; i++) {
        int src = g_csrc[i];
        const float4* f = (const float4*)&g_feat[(size_t)(p * NN + src) * HD];
        float ex = 0.f;
        if (lane < HH) {
            float el = g_el[(p * NN + src) * HH + lane];
            ex = __expf(lrelu(el + er_h));
            den += ex;
        }
        float e0 = __shfl_sync(0xffffffffu, ex, hsel);
        float e1 = __shfl_sync(0xffffffffu, ex, 4 + hsel);
        float4 v0 = f[lane];
        float4 v1 = f[32 + lane];
        acc0.x += v0.x * e0; acc0.y += v0.y * e0;
        acc0.z += v0.z * e0; acc0.w += v0.w * e0;
        acc1.x += v1.x * e1; acc1.y += v1.y * e1;
        acc1.z += v1.z * e1; acc1.w += v1.w * e1;
    }

    float inv = 0.f;
    if (lane < HH) inv = (den > 0.f) ? 1.f / den : 0.f;
    float i0 = __shfl_sync(0xffffffffu, inv, hsel);
    float i1 = __shfl_sync(0xffffffffu, inv, 4 + hsel);

    float4 z0, z1;
    z0.x = acc0.x * i0; z0.y = acc0.y * i0; z0.z = acc0.z * i0; z0.w = acc0.w * i0;
    z1.x = acc1.x * i1; z1.y = acc1.y * i1; z1.z = acc1.z * i1; z1.w = acc1.w * i1;
    z0.x = z0.x > 0.f ? z0.x : expm1f(z0.x);
    z0.y = z0.y > 0.f ? z0.y : expm1f(z0.y);
    z0.z = z0.z > 0.f ? z0.z : expm1f(z0.z);
    z0.w = z0.w > 0.f ? z0.w : expm1f(z0.w);
    z1.x = z1.x > 0.f ? z1.x : expm1f(z1.x);
    z1.y = z1.y > 0.f ? z1.y : expm1f(z1.y);
    z1.z = z1.z > 0.f ? z1.z : expm1f(z1.z);
    z1.w = z1.w > 0.f ? z1.w : expm1f(z1.w);

    float4* zp = (float4*)&g_z[(size_t)w * HD];
    zp[lane]      = z0;
    zp[32 + lane] = z1;
}

// -------- K6: out = zcat @ sem_w + sem_b. 128x128 tile, double-buffered, K=768 --------
__global__ void __launch_bounds__(256, 2)
k_gemm_out(const float* __restrict__ sw, const float* __restrict__ sb,
           float* __restrict__ out) {
    const int m0 = blockIdx.x * 128;

    __shared__ float As[2][16][132];
    __shared__ float Bs[2][16][128];

    const int tid = threadIdx.x;
    const int tx  = tid & 15;
    const int ty  = tid >> 4;

    const int rowA = tid >> 2;
    const int kgA  = (tid & 3) * 4;
    const int kB   = tid >> 5;
    const int nB   = (tid & 31) * 4;

    float4 ra0, ra1, rb0, rb1;
    float acc[8][8] = {};
    const float4 f4z = make_float4(0.f, 0.f, 0.f, 0.f);

    // preload chunk 0
    {
        int gr0 = m0 + rowA, gr1 = m0 + rowA + 64;
        ra0 = (gr0 < NN) ? *(const float4*)&g_z[(size_t)gr0 * HD + kgA] : f4z;
        ra1 = (gr1 < NN) ? *(const float4*)&g_z[(size_t)gr1 * HD + kgA] : f4z;
        rb0 = *(const float4*)&sw[(size_t)kB * EMB + nB];
        rb1 = *(const float4*)&sw[(size_t)(kB + 8) * EMB + nB];
        As[0][kgA + 0][rowA] = ra0.x; As[0][kgA + 1][rowA] = ra0.y;
        As[0][kgA + 2][rowA] = ra0.z; As[0][kgA + 3][rowA] = ra0.w;
        As[0][kgA + 0][rowA + 64] = ra1.x; As[0][kgA + 1][rowA + 64] = ra1.y;
        As[0][kgA + 2][rowA + 64] = ra1.z; As[0][kgA + 3][rowA + 64] = ra1.w;
        *(float4*)&Bs[0][kB][nB]     = rb0;
        *(float4*)&Bs[0][kB + 8][nB] = rb1;
    }
    __syncthreads();

    for (int it = 0; it < 48; it++) {
        const int cur = it & 1;
        if (it < 47) {
            int kc  = (it + 1) * 16;
            int pch = kc >> 8;
            int kk0 = kc & 255;
            int gr0 = m0 + rowA, gr1 = m0 + rowA + 64;
            ra0 = (gr0 < NN) ? *(const float4*)&g_z[((size_t)pch * NN + gr0) * HD + kk0 + kgA] : f4z;
            ra1 = (gr1 < NN) ? *(const float4*)&g_z[((size_t)pch * NN + gr1) * HD + kk0 + kgA] : f4z;
            rb0 = *(const float4*)&sw[(size_t)(kc + kB) * EMB + nB];
            rb1 = *(const float4*)&sw[(size_t)(kc + kB + 8) * EMB + nB];
        }
        float (*A)[132] = As[cur];
        float (*B)[128] = Bs[cur];
#pragma unroll
        for (int k = 0; k < 16; k++) {
            float4 a0 = *(float4*)&A[k][ty * 8];
            float4 a1 = *(float4*)&A[k][ty * 8 + 4];
            float4 b0 = *(float4*)&B[k][tx * 8];
            float4 b1 = *(float4*)&B[k][tx * 8 + 4];
            float a[8] = {a0.x, a0.y, a0.z, a0.w, a1.x, a1.y, a1.z, a1.w};
            float b[8] = {b0.x, b0.y, b0.z, b0.w, b1.x, b1.y, b1.z, b1.w};
#pragma unroll
            for (int i = 0; i < 8; i++)
#pragma unroll
                for (int j2 = 0; j2 < 8; j2++) acc[i][j2] += a[i] * b[j2];
        }
        if (it < 47) {
            const int nxt = cur ^ 1;
            As[nxt][kgA + 0][rowA] = ra0.x; As[nxt][kgA + 1][rowA] = ra0.y;
            As[nxt][kgA + 2][rowA] = ra0.z; As[nxt][kgA + 3][rowA] = ra0.w;
            As[nxt][kgA + 0][rowA + 64] = ra1.x; As[nxt][kgA + 1][rowA + 64] = ra1.y;
            As[nxt][kgA + 2][rowA + 64] = ra1.z; As[nxt][kgA + 3][rowA + 64] = ra1.w;
            *(float4*)&Bs[nxt][kB][nB]     = rb0;
            *(float4*)&Bs[nxt][kB + 8][nB] = rb1;
        }
        __syncthreads();
    }

    float bias[8];
#pragma unroll
    for (int j = 0; j < 8; j++) bias[j] = sb[tx * 8 + j];
#pragma unroll
    for (int i = 0; i < 8; i++) {
        int row = m0 + ty * 8 + i;
        if (row >= NN) continue;
        float4 v0 = make_float4(acc[i][0] + bias[0], acc[i][1] + bias[1],
                                acc[i][2] + bias[2], acc[i][3] + bias[3]);
        float4 v1 = make_float4(acc[i][4] + bias[4], acc[i][5] + bias[5],
                                acc[i][6] + bias[6], acc[i][7] + bias[7]);
        float* op = &out[(size_t)row * EMB + tx * 8];
        *(float4*)op       = v0;
        *(float4*)(op + 4) = v1;
    }
}

extern "C" void kernel_launch(void* const* d_in, const int* in_sizes, int n_in,
                              void* d_out, int out_size) {
    const float* h  = (const float*)d_in[0];
    const int*   ei = (const int*)  d_in[1];
    const float* fw = (const float*)d_in[2];
    const float* al = (const float*)d_in[3];
    const float* ar = (const float*)d_in[4];
    const float* sw = (const float*)d_in[5];
    const float* sb = (const float*)d_in[6];
    float* out = (float*)d_out;

    k_zero_deg<<<(M_ROWS + 255) / 256, 256>>>();                 // 1
    k_hist<<<(PP * EE + 255) / 256, 256>>>(ei);                  // 2
    k_scan1<<<NBLK_SCAN, 256>>>();                               // 3

    dim3 g1((NN + 127) / 128, HD / 128, PP);
    k_gemm_feat<<<g1, 256>>>(h, fw, al, ar);                     // 4 (profiled)

    k_scan23<<<(M_ROWS + 255) / 256, 256>>>();                   // 5
    k_scatter<<<(PP * EE + 255) / 256, 256>>>(ei);               // 6

    k_gather<<<(M_ROWS + 7) / 8, 256>>>();                       // 7

    k_gemm_out<<<(NN + 127) / 128, 256>>>(sw, sb, out);          // 8
}

// round 9
// speedup vs baseline: 1.0509x; 1.0509x over previous
#include <cuda_runtime.h>
#include <math_constants.h>

#define NN     50000
#define EE     800000
#define PP     3
#define INF_   128
#define HH     8
#define DD     32
#define HD     256
#define EMB    128
#define KTOT   768
#define M_ROWS (PP * NN)
#define NBLK_SCAN ((M_ROWS + 2047) / 2048)

// -------- device scratch --------
__device__ float g_feat[(size_t)PP * NN * HD];
__device__ float g_z   [(size_t)PP * NN * HD];
__device__ float g_el  [M_ROWS * HH];
__device__ float g_er  [M_ROWS * HH];
__device__ int   g_deg [M_ROWS];
__device__ int   g_off [M_ROWS];
__device__ int   g_cur [M_ROWS];
__device__ int   g_bsum[256];
__device__ int   g_csrc[PP * EE];

__device__ __forceinline__ float lrelu(float x) { return x > 0.f ? x : 0.2f * x; }

// -------- CSR build --------
__global__ void k_zero_deg() {
    int i = blockIdx.x * blockDim.x + threadIdx.x;
    if (i < M_ROWS) g_deg[i] = 0;
}

__global__ void k_hist(const int* __restrict__ ei) {
    int id = blockIdx.x * blockDim.x + threadIdx.x;
    if (id >= PP * EE) return;
    int p = id / EE, e = id - p * EE;
    int dst = ei[(size_t)p * 2 * EE + EE + e];
    atomicAdd(&g_deg[p * NN + dst], 1);
}

__global__ void k_scan1() {
    __shared__ int sd[256];
    int b = blockIdx.x, t = threadIdx.x;
    int base = b * 2048 + t * 8;
    int v[8]; int s = 0;
#pragma unroll
    for (int i = 0; i < 8; i++) {
        int x = (base + i < M_ROWS) ? g_deg[base + i] : 0;
        v[i] = s; s += x;
    }
    sd[t] = s; __syncthreads();
    for (int off = 1; off < 256; off <<= 1) {
        int x = (t >= off) ? sd[t - off] : 0;
        __syncthreads();
        sd[t] += x;
        __syncthreads();
    }
    int exc = sd[t] - s;
#pragma unroll
    for (int i = 0; i < 8; i++)
        if (base + i < M_ROWS) g_off[base + i] = exc + v[i];
    if (t == 255) g_bsum[b] = sd[255];
}

__global__ void k_scan23() {
    __shared__ int sb[NBLK_SCAN];
    if (threadIdx.x < NBLK_SCAN) sb[threadIdx.x] = g_bsum[threadIdx.x];
    __syncthreads();
    int i = blockIdx.x * blockDim.x + threadIdx.x;
    if (i >= M_ROWS) return;
    int b = i >> 11;
    int s = 0;
    for (int j = 0; j < b; j++) s += sb[j];
    int o = g_off[i] + s;
    g_off[i] = o;
    g_cur[i] = o;
}

__global__ void k_scatter(const int* __restrict__ ei) {
    int id = blockIdx.x * blockDim.x + threadIdx.x;
    if (id >= PP * EE) return;
    int p = id / EE, e = id - p * EE;
    int src = ei[(size_t)p * 2 * EE + e];
    int dst = ei[(size_t)p * 2 * EE + EE + e];
    int pos = atomicAdd(&g_cur[p * NN + dst], 1);
    g_csrc[pos] = src;
}

// -------- K1: feat = h @ fc_w, fused el/er. 128x128 tile, 8x8 micro, k-chunk 32 --------
__global__ void __launch_bounds__(256, 2)
k_gemm_feat(const float* __restrict__ hmat, const float* __restrict__ fw,
            const float* __restrict__ al, const float* __restrict__ ar) {
    const int p  = blockIdx.z;
    const int m0 = blockIdx.x * 128;
    const int n0 = blockIdx.y * 128;
    const float* W = fw + (size_t)p * INF_ * HD;

    __shared__ float As[32][132];   // [k][m]
    __shared__ float Bs[32][128];   // [k][n]

    const int tid = threadIdx.x;
    const int tx  = tid & 15;
    const int ty  = tid >> 4;
    float acc[8][8] = {};

    float alv[8], arv[8];
#pragma unroll
    for (int j = 0; j < 8; j++) {
        alv[j] = al[p * HD + n0 + tx * 8 + j];
        arv[j] = ar[p * HD + n0 + tx * 8 + j];
    }

    for (int kc = 0; kc < INF_; kc += 32) {
#pragma unroll
        for (int j = 0; j < 4; j++) {            // A: 128 rows x 32 k = 1024 float4
            int t   = tid + j * 256;
            int row = t >> 3;
            int kg  = (t & 7) * 4;
            int gr  = m0 + row;
            float4 v = make_float4(0.f, 0.f, 0.f, 0.f);
            if (gr < NN) v = *(const float4*)&hmat[(size_t)gr * INF_ + kc + kg];
            As[kg + 0][row] = v.x; As[kg + 1][row] = v.y;
            As[kg + 2][row] = v.z; As[kg + 3][row] = v.w;
        }
#pragma unroll
        for (int j = 0; j < 4; j++) {            // B: 32 k x 128 n = 1024 float4
            int t = tid + j * 256;
            int k = t >> 5;
            int n = (t & 31) * 4;
            *(float4*)&Bs[k][n] = *(const float4*)&W[(size_t)(kc + k) * HD + n0 + n];
        }
        __syncthreads();
#pragma unroll
        for (int k = 0; k < 32; k++) {
            float4 a0 = *(float4*)&As[k][ty * 8];
            float4 a1 = *(float4*)&As[k][ty * 8 + 4];
            float4 b0 = *(float4*)&Bs[k][tx * 8];
            float4 b1 = *(float4*)&Bs[k][tx * 8 + 4];
            float a[8] = {a0.x, a0.y, a0.z, a0.w, a1.x, a1.y, a1.z, a1.w};
            float b[8] = {b0.x, b0.y, b0.z, b0.w, b1.x, b1.y, b1.z, b1.w};
#pragma unroll
            for (int i = 0; i < 8; i++)
#pragma unroll
                for (int j = 0; j < 8; j++) acc[i][j] += a[i] * b[j];
        }
        __syncthreads();
    }

    const int h = (n0 >> 5) + (tx >> 2);
#pragma unroll
    for (int i = 0; i < 8; i++) {
        int row = m0 + ty * 8 + i;
        if (row < NN) {
            float4 v0 = make_float4(acc[i][0], acc[i][1], acc[i][2], acc[i][3]);
            float4 v1 = make_float4(acc[i][4], acc[i][5], acc[i][6], acc[i][7]);
            float* fp = &g_feat[((size_t)p * NN + row) * HD + n0 + tx * 8];
            *(float4*)fp       = v0;
            *(float4*)(fp + 4) = v1;
        }
        float pel = 0.f, per = 0.f;
#pragma unroll
        for (int j = 0; j < 8; j++) {
            pel += acc[i][j] * alv[j];
            per += acc[i][j] * arv[j];
        }
        pel += __shfl_xor_sync(0xffffffffu, pel, 1);
        pel += __shfl_xor_sync(0xffffffffu, pel, 2);
        per += __shfl_xor_sync(0xffffffffu, per, 1);
        per += __shfl_xor_sync(0xffffffffu, per, 2);
        if ((tx & 3) == 0 && row < NN) {
            g_el[(p * NN + row) * HH + h] = pel;
            g_er[(p * NN + row) * HH + h] = per;
        }
    }
}

// -------- K3: single-pass softmax + aggregate + ELU, warp per (p,dst), unroll 4 --------
__global__ void k_gather() {
    int w    = (int)((blockIdx.x * (size_t)blockDim.x + threadIdx.x) >> 5);
    int lane = threadIdx.x & 31;
    if (w >= M_ROWS) return;
    int p   = w / NN;
    int beg = g_off[w];
    int end = beg + g_deg[w];

    float er_h = (lane < HH) ? g_er[w * HH + lane] : 0.f;

    float4 acc0 = make_float4(0.f, 0.f, 0.f, 0.f);
    float4 acc1 = make_float4(0.f, 0.f, 0.f, 0.f);
    float  den  = 0.f;
    const int hsel = lane >> 3;

    int i = beg;
    for (; i + 4 <= end; i += 4) {
        int s0 = g_csrc[i];
        int s1 = g_csrc[i + 1];
        int s2 = g_csrc[i + 2];
        int s3 = g_csrc[i + 3];
        const float4* f0 = (const float4*)&g_feat[(size_t)(p * NN + s0) * HD];
        const float4* f1 = (const float4*)&g_feat[(size_t)(p * NN + s1) * HD];
        const float4* f2 = (const float4*)&g_feat[(size_t)(p * NN + s2) * HD];
        const float4* f3 = (const float4*)&g_feat[(size_t)(p * NN + s3) * HD];
        float ex0 = 0.f, ex1 = 0.f, ex2 = 0.f, ex3 = 0.f;
        if (lane < HH) {
            float el0 = g_el[(p * NN + s0) * HH + lane];
            float el1 = g_el[(p * NN + s1) * HH + lane];
            float el2 = g_el[(p * NN + s2) * HH + lane];
            float el3 = g_el[(p * NN + s3) * HH + lane];
            ex0 = __expf(lrelu(el0 + er_h));
            ex1 = __expf(lrelu(el1 + er_h));
            ex2 = __expf(lrelu(el2 + er_h));
            ex3 = __expf(lrelu(el3 + er_h));
            den += (ex0 + ex1) + (ex2 + ex3);
        }
        float4 u0 = f0[lane],      u1 = f0[32 + lane];
        float4 v0 = f1[lane],      v1 = f1[32 + lane];
        float4 w0 = f2[lane],      w1 = f2[32 + lane];
        float4 x0 = f3[lane],      x1 = f3[32 + lane];
        float e00 = __shfl_sync(0xffffffffu, ex0, hsel);
        float e01 = __shfl_sync(0xffffffffu, ex0, 4 + hsel);
        float e10 = __shfl_sync(0xffffffffu, ex1, hsel);
        float e11 = __shfl_sync(0xffffffffu, ex1, 4 + hsel);
        float e20 = __shfl_sync(0xffffffffu, ex2, hsel);
        float e21 = __shfl_sync(0xffffffffu, ex2, 4 + hsel);
        float e30 = __shfl_sync(0xffffffffu, ex3, hsel);
        float e31 = __shfl_sync(0xffffffffu, ex3, 4 + hsel);
        acc0.x += u0.x * e00 + v0.x * e10 + w0.x * e20 + x0.x * e30;
        acc0.y += u0.y * e00 + v0.y * e10 + w0.y * e20 + x0.y * e30;
        acc0.z += u0.z * e00 + v0.z * e10 + w0.z * e20 + x0.z * e30;
        acc0.w += u0.w * e00 + v0.w * e10 + w0.w * e20 + x0.w * e30;
        acc1.x += u1.x * e01 + v1.x * e11 + w1.x * e21 + x1.x * e31;
        acc1.y += u1.y * e01 + v1.y * e11 + w1.y * e21 + x1.y * e31;
        acc1.z += u1.z * e01 + v1.z * e11 + w1.z * e21 + x1.z * e31;
        acc1.w += u1.w * e01 + v1.w * e11 + w1.w * e21 + x1.w * e31;
    }
    for (; i < end; i++) {
        int src = g_csrc[i];
        const float4* f = (const float4*)&g_feat[(size_t)(p * NN + src) * HD];
        float ex = 0.f;
        if (lane < HH) {
            float el = g_el[(p * NN + src) * HH + lane];
            ex = __expf(lrelu(el + er_h));
            den += ex;
        }
        float e0 = __shfl_sync(0xffffffffu, ex, hsel);
        float e1 = __shfl_sync(0xffffffffu, ex, 4 + hsel);
        float4 v0 = f[lane];
        float4 v1 = f[32 + lane];
        acc0.x += v0.x * e0; acc0.y += v0.y * e0;
        acc0.z += v0.z * e0; acc0.w += v0.w * e0;
        acc1.x += v1.x * e1; acc1.y += v1.y * e1;
        acc1.z += v1.z * e1; acc1.w += v1.w * e1;
    }

    float inv = 0.f;
    if (lane < HH) inv = (den > 0.f) ? 1.f / den : 0.f;
    float i0 = __shfl_sync(0xffffffffu, inv, hsel);
    float i1 = __shfl_sync(0xffffffffu, inv, 4 + hsel);

    float4 z0, z1;
    z0.x = acc0.x * i0; z0.y = acc0.y * i0; z0.z = acc0.z * i0; z0.w = acc0.w * i0;
    z1.x = acc1.x * i1; z1.y = acc1.y * i1; z1.z = acc1.z * i1; z1.w = acc1.w * i1;
    z0.x = z0.x > 0.f ? z0.x : expm1f(z0.x);
    z0.y = z0.y > 0.f ? z0.y : expm1f(z0.y);
    z0.z = z0.z > 0.f ? z0.z : expm1f(z0.z);
    z0.w = z0.w > 0.f ? z0.w : expm1f(z0.w);
    z1.x = z1.x > 0.f ? z1.x : expm1f(z1.x);
    z1.y = z1.y > 0.f ? z1.y : expm1f(z1.y);
    z1.z = z1.z > 0.f ? z1.z : expm1f(z1.z);
    z1.w = z1.w > 0.f ? z1.w : expm1f(z1.w);

    float4* zp = (float4*)&g_z[(size_t)w * HD];
    zp[lane]      = z0;
    zp[32 + lane] = z1;
}

// -------- K6: out = zcat @ sem_w + sem_b. 128x128 tile, 8x8 micro, k-chunk 32 --------
__global__ void __launch_bounds__(256, 2)
k_gemm_out(const float* __restrict__ sw, const float* __restrict__ sb,
           float* __restrict__ out) {
    const int m0 = blockIdx.x * 128;

    __shared__ float As[32][132];
    __shared__ float Bs[32][128];

    const int tid = threadIdx.x;
    const int tx  = tid & 15;
    const int ty  = tid >> 4;
    float acc[8][8] = {};

    for (int kc = 0; kc < KTOT; kc += 32) {
        const int pch = kc >> 8;
        const int kk0 = kc & 255;
#pragma unroll
        for (int j = 0; j < 4; j++) {            // A: 128 rows x 32 k from g_z
            int t   = tid + j * 256;
            int row = t >> 3;
            int kg  = (t & 7) * 4;
            int gr  = m0 + row;
            float4 v = make_float4(0.f, 0.f, 0.f, 0.f);
            if (gr < NN)
                v = *(const float4*)&g_z[((size_t)pch * NN + gr) * HD + kk0 + kg];
            As[kg + 0][row] = v.x; As[kg + 1][row] = v.y;
            As[kg + 2][row] = v.z; As[kg + 3][row] = v.w;
        }
#pragma unroll
        for (int j = 0; j < 4; j++) {            // B: 32 k x 128 n
            int t = tid + j * 256;
            int k = t >> 5;
            int n = (t & 31) * 4;
            *(float4*)&Bs[k][n] = *(const float4*)&sw[(size_t)(kc + k) * EMB + n];
        }
        __syncthreads();
#pragma unroll
        for (int k = 0; k < 32; k++) {
            float4 a0 = *(float4*)&As[k][ty * 8];
            float4 a1 = *(float4*)&As[k][ty * 8 + 4];
            float4 b0 = *(float4*)&Bs[k][tx * 8];
            float4 b1 = *(float4*)&Bs[k][tx * 8 + 4];
            float a[8] = {a0.x, a0.y, a0.z, a0.w, a1.x, a1.y, a1.z, a1.w};
            float b[8] = {b0.x, b0.y, b0.z, b0.w, b1.x, b1.y, b1.z, b1.w};
#pragma unroll
            for (int i = 0; i < 8; i++)
#pragma unroll
                for (int j2 = 0; j2 < 8; j2++) acc[i][j2] += a[i] * b[j2];
        }
        __syncthreads();
    }

    float bias[8];
#pragma unroll
    for (int j = 0; j < 8; j++) bias[j] = sb[tx * 8 + j];
#pragma unroll
    for (int i = 0; i < 8; i++) {
        int row = m0 + ty * 8 + i;
        if (row >= NN) continue;
        float4 v0 = make_float4(acc[i][0] + bias[0], acc[i][1] + bias[1],
                                acc[i][2] + bias[2], acc[i][3] + bias[3]);
        float4 v1 = make_float4(acc[i][4] + bias[4], acc[i][5] + bias[5],
                                acc[i][6] + bias[6], acc[i][7] + bias[7]);
        float* op = &out[(size_t)row * EMB + tx * 8];
        *(float4*)op       = v0;
        *(float4*)(op + 4) = v1;
    }
}

extern "C" void kernel_launch(void* const* d_in, const int* in_sizes, int n_in,
                              void* d_out, int out_size) {
    const float* h  = (const float*)d_in[0];
    const int*   ei = (const int*)  d_in[1];
    const float* fw = (const float*)d_in[2];
    const float* al = (const float*)d_in[3];
    const float* ar = (const float*)d_in[4];
    const float* sw = (const float*)d_in[5];
    const float* sb = (const float*)d_in[6];
    float* out = (float*)d_out;

    k_zero_deg<<<(M_ROWS + 255) / 256, 256>>>();                 // 1
    k_hist<<<(PP * EE + 255) / 256, 256>>>(ei);                  // 2
    k_scan1<<<NBLK_SCAN, 256>>>();                               // 3

    dim3 g1((NN + 127) / 128, HD / 128, PP);
    k_gemm_feat<<<g1, 256>>>(h, fw, al, ar);                     // 4 (profiled)

    k_scan23<<<(M_ROWS + 255) / 256, 256>>>();                   // 5
    k_scatter<<<(PP * EE + 255) / 256, 256>>>(ei);               // 6

    k_gather<<<(M_ROWS + 7) / 8, 256>>>();                       // 7

    k_gemm_out<<<(NN + 127) / 128, 256>>>(sw, sb, out);          // 8
}

// round 11
// speedup vs baseline: 1.0657x; 1.0141x over previous
#include <cuda_runtime.h>
#include <math_constants.h>

#define NN     50000
#define EE     800000
#define PP     3
#define INF_   128
#define HH     8
#define DD     32
#define HD     256
#define EMB    128
#define KTOT   768
#define M_ROWS (PP * NN)
#define NBLK_SCAN ((M_ROWS + 2047) / 2048)

// -------- device scratch --------
__device__ float g_feat[(size_t)PP * NN * HD];
__device__ float g_z   [(size_t)PP * NN * HD];
__device__ float g_el  [M_ROWS * HH];
__device__ float g_er  [M_ROWS * HH];
__device__ int   g_deg [M_ROWS];
__device__ int   g_off [M_ROWS];
__device__ int   g_cur [M_ROWS];
__device__ int   g_bsum[256];
__device__ int   g_csrc[PP * EE];

__device__ __forceinline__ float lrelu(float x) { return x > 0.f ? x : 0.2f * x; }

// -------- CSR build --------
__global__ void k_zero_deg() {
    int i = blockIdx.x * blockDim.x + threadIdx.x;
    if (i < M_ROWS) g_deg[i] = 0;
}

__global__ void k_hist(const int* __restrict__ ei) {
    int id = blockIdx.x * blockDim.x + threadIdx.x;
    if (id >= PP * EE) return;
    int p = id / EE, e = id - p * EE;
    int dst = ei[(size_t)p * 2 * EE + EE + e];
    atomicAdd(&g_deg[p * NN + dst], 1);
}

__global__ void k_scan1() {
    __shared__ int sd[256];
    int b = blockIdx.x, t = threadIdx.x;
    int base = b * 2048 + t * 8;
    int v[8]; int s = 0;
#pragma unroll
    for (int i = 0; i < 8; i++) {
        int x = (base + i < M_ROWS) ? g_deg[base + i] : 0;
        v[i] = s; s += x;
    }
    sd[t] = s; __syncthreads();
    for (int off = 1; off < 256; off <<= 1) {
        int x = (t >= off) ? sd[t - off] : 0;
        __syncthreads();
        sd[t] += x;
        __syncthreads();
    }
    int exc = sd[t] - s;
#pragma unroll
    for (int i = 0; i < 8; i++)
        if (base + i < M_ROWS) g_off[base + i] = exc + v[i];
    if (t == 255) g_bsum[b] = sd[255];
}

__global__ void k_scan23() {
    __shared__ int sb[NBLK_SCAN];
    if (threadIdx.x < NBLK_SCAN) sb[threadIdx.x] = g_bsum[threadIdx.x];
    __syncthreads();
    int i = blockIdx.x * blockDim.x + threadIdx.x;
    if (i >= M_ROWS) return;
    int b = i >> 11;
    int s = 0;
    for (int j = 0; j < b; j++) s += sb[j];
    int o = g_off[i] + s;
    g_off[i] = o;
    g_cur[i] = o;
}

__global__ void k_scatter(const int* __restrict__ ei) {
    int id = blockIdx.x * blockDim.x + threadIdx.x;
    if (id >= PP * EE) return;
    int p = id / EE, e = id - p * EE;
    int src = ei[(size_t)p * 2 * EE + e];
    int dst = ei[(size_t)p * 2 * EE + EE + e];
    int pos = atomicAdd(&g_cur[p * NN + dst], 1);
    g_csrc[pos] = src;
}

// -------- K1: feat = h @ fc_w, fused el/er. 128x128 tile, split-N 8x8 micro --------
// Thread owns cols [tx*4, tx*4+4) and [64+tx*4, 64+tx*4+4): conflict-free LDS.128.
__global__ void __launch_bounds__(256, 2)
k_gemm_feat(const float* __restrict__ hmat, const float* __restrict__ fw,
            const float* __restrict__ al, const float* __restrict__ ar) {
    const int p  = blockIdx.z;
    const int m0 = blockIdx.x * 128;
    const int n0 = blockIdx.y * 128;
    const float* W = fw + (size_t)p * INF_ * HD;

    __shared__ float As[32][132];   // [k][m]
    __shared__ float Bs[32][128];   // [k][n]

    const int tid = threadIdx.x;
    const int tx  = tid & 15;
    const int ty  = tid >> 4;
    float acc[8][8] = {};           // [row][0..3 = lo cols, 4..7 = hi cols]

    float alv0[4], arv0[4], alv1[4], arv1[4];
#pragma unroll
    for (int j = 0; j < 4; j++) {
        alv0[j] = al[p * HD + n0 + tx * 4 + j];
        arv0[j] = ar[p * HD + n0 + tx * 4 + j];
        alv1[j] = al[p * HD + n0 + 64 + tx * 4 + j];
        arv1[j] = ar[p * HD + n0 + 64 + tx * 4 + j];
    }

    for (int kc = 0; kc < INF_; kc += 32) {
#pragma unroll
        for (int j = 0; j < 4; j++) {            // A: 128 rows x 32 k = 1024 float4
            int t   = tid + j * 256;
            int row = t >> 3;
            int kg  = (t & 7) * 4;
            int gr  = m0 + row;
            float4 v = make_float4(0.f, 0.f, 0.f, 0.f);
            if (gr < NN) v = *(const float4*)&hmat[(size_t)gr * INF_ + kc + kg];
            As[kg + 0][row] = v.x; As[kg + 1][row] = v.y;
            As[kg + 2][row] = v.z; As[kg + 3][row] = v.w;
        }
#pragma unroll
        for (int j = 0; j < 4; j++) {            // B: 32 k x 128 n = 1024 float4
            int t = tid + j * 256;
            int k = t >> 5;
            int n = (t & 31) * 4;
            *(float4*)&Bs[k][n] = *(const float4*)&W[(size_t)(kc + k) * HD + n0 + n];
        }
        __syncthreads();
#pragma unroll
        for (int k = 0; k < 32; k++) {
            float4 a0 = *(float4*)&As[k][ty * 8];
            float4 a1 = *(float4*)&As[k][ty * 8 + 4];
            float4 b0 = *(float4*)&Bs[k][tx * 4];        // 16B stride: conflict-free
            float4 b1 = *(float4*)&Bs[k][64 + tx * 4];
            float a[8] = {a0.x, a0.y, a0.z, a0.w, a1.x, a1.y, a1.z, a1.w};
            float b[8] = {b0.x, b0.y, b0.z, b0.w, b1.x, b1.y, b1.z, b1.w};
#pragma unroll
            for (int i = 0; i < 8; i++)
#pragma unroll
                for (int j = 0; j < 8; j++) acc[i][j] += a[i] * b[j];
        }
        __syncthreads();
    }

    const int h0 = (n0 >> 5) + (tx >> 3);        // head for lo 4 cols
    const int h1 = h0 + 2;                       // head for hi 4 cols
#pragma unroll
    for (int i = 0; i < 8; i++) {
        int row = m0 + ty * 8 + i;
        if (row < NN) {
            float4 v0 = make_float4(acc[i][0], acc[i][1], acc[i][2], acc[i][3]);
            float4 v1 = make_float4(acc[i][4], acc[i][5], acc[i][6], acc[i][7]);
            float* fp = &g_feat[((size_t)p * NN + row) * HD + n0 + tx * 4];
            *(float4*)fp        = v0;
            *(float4*)(fp + 64) = v1;
        }
        float pel0 = 0.f, per0 = 0.f, pel1 = 0.f, per1 = 0.f;
#pragma unroll
        for (int j = 0; j < 4; j++) {
            pel0 += acc[i][j]     * alv0[j];
            per0 += acc[i][j]     * arv0[j];
            pel1 += acc[i][j + 4] * alv1[j];
            per1 += acc[i][j + 4] * arv1[j];
        }
#pragma unroll
        for (int o = 1; o <= 4; o <<= 1) {       // reduce across tx octet (lane bits 0-2)
            pel0 += __shfl_xor_sync(0xffffffffu, pel0, o);
            per0 += __shfl_xor_sync(0xffffffffu, per0, o);
            pel1 += __shfl_xor_sync(0xffffffffu, pel1, o);
            per1 += __shfl_xor_sync(0xffffffffu, per1, o);
        }
        if ((tx & 7) == 0 && row < NN) {
            g_el[(p * NN + row) * HH + h0] = pel0;
            g_er[(p * NN + row) * HH + h0] = per0;
            g_el[(p * NN + row) * HH + h1] = pel1;
            g_er[(p * NN + row) * HH + h1] = per1;
        }
    }
}

// -------- K3: single-pass softmax + aggregate + ELU, warp per (p,dst), unroll 4 --------
__global__ void k_gather() {
    int w    = (int)((blockIdx.x * (size_t)blockDim.x + threadIdx.x) >> 5);
    int lane = threadIdx.x & 31;
    if (w >= M_ROWS) return;
    int p   = w / NN;
    int beg = g_off[w];
    int end = beg + g_deg[w];

    float er_h = (lane < HH) ? g_er[w * HH + lane] : 0.f;

    float4 acc0 = make_float4(0.f, 0.f, 0.f, 0.f);
    float4 acc1 = make_float4(0.f, 0.f, 0.f, 0.f);
    float  den  = 0.f;
    const int hsel = lane >> 3;

    int i = beg;
    for (; i + 4 <= end; i += 4) {
        int s0 = g_csrc[i];
        int s1 = g_csrc[i + 1];
        int s2 = g_csrc[i + 2];
        int s3 = g_csrc[i + 3];
        const float4* f0 = (const float4*)&g_feat[(size_t)(p * NN + s0) * HD];
        const float4* f1 = (const float4*)&g_feat[(size_t)(p * NN + s1) * HD];
        const float4* f2 = (const float4*)&g_feat[(size_t)(p * NN + s2) * HD];
        const float4* f3 = (const float4*)&g_feat[(size_t)(p * NN + s3) * HD];
        float ex0 = 0.f, ex1 = 0.f, ex2 = 0.f, ex3 = 0.f;
        if (lane < HH) {
            float el0 = g_el[(p * NN + s0) * HH + lane];
            float el1 = g_el[(p * NN + s1) * HH + lane];
            float el2 = g_el[(p * NN + s2) * HH + lane];
            float el3 = g_el[(p * NN + s3) * HH + lane];
            ex0 = __expf(lrelu(el0 + er_h));
            ex1 = __expf(lrelu(el1 + er_h));
            ex2 = __expf(lrelu(el2 + er_h));
            ex3 = __expf(lrelu(el3 + er_h));
            den += (ex0 + ex1) + (ex2 + ex3);
        }
        float4 u0 = f0[lane],      u1 = f0[32 + lane];
        float4 v0 = f1[lane],      v1 = f1[32 + lane];
        float4 w0 = f2[lane],      w1 = f2[32 + lane];
        float4 x0 = f3[lane],      x1 = f3[32 + lane];
        float e00 = __shfl_sync(0xffffffffu, ex0, hsel);
        float e01 = __shfl_sync(0xffffffffu, ex0, 4 + hsel);
        float e10 = __shfl_sync(0xffffffffu, ex1, hsel);
        float e11 = __shfl_sync(0xffffffffu, ex1, 4 + hsel);
        float e20 = __shfl_sync(0xffffffffu, ex2, hsel);
        float e21 = __shfl_sync(0xffffffffu, ex2, 4 + hsel);
        float e30 = __shfl_sync(0xffffffffu, ex3, hsel);
        float e31 = __shfl_sync(0xffffffffu, ex3, 4 + hsel);
        acc0.x += u0.x * e00 + v0.x * e10 + w0.x * e20 + x0.x * e30;
        acc0.y += u0.y * e00 + v0.y * e10 + w0.y * e20 + x0.y * e30;
        acc0.z += u0.z * e00 + v0.z * e10 + w0.z * e20 + x0.z * e30;
        acc0.w += u0.w * e00 + v0.w * e10 + w0.w * e20 + x0.w * e30;
        acc1.x += u1.x * e01 + v1.x * e11 + w1.x * e21 + x1.x * e31;
        acc1.y += u1.y * e01 + v1.y * e11 + w1.y * e21 + x1.y * e31;
        acc1.z += u1.z * e01 + v1.z * e11 + w1.z * e21 + x1.z * e31;
        acc1.w += u1.w * e01 + v1.w * e11 + w1.w * e21 + x1.w * e31;
    }
    for (; i < end; i++) {
        int src = g_csrc[i];
        const float4* f = (const float4*)&g_feat[(size_t)(p * NN + src) * HD];
        float ex = 0.f;
        if (lane < HH) {
            float el = g_el[(p * NN + src) * HH + lane];
            ex = __expf(lrelu(el + er_h));
            den += ex;
        }
        float e0 = __shfl_sync(0xffffffffu, ex, hsel);
        float e1 = __shfl_sync(0xffffffffu, ex, 4 + hsel);
        float4 v0 = f[lane];
        float4 v1 = f[32 + lane];
        acc0.x += v0.x * e0; acc0.y += v0.y * e0;
        acc0.z += v0.z * e0; acc0.w += v0.w * e0;
        acc1.x += v1.x * e1; acc1.y += v1.y * e1;
        acc1.z += v1.z * e1; acc1.w += v1.w * e1;
    }

    float inv = 0.f;
    if (lane < HH) inv = (den > 0.f) ? 1.f / den : 0.f;
    float i0 = __shfl_sync(0xffffffffu, inv, hsel);
    float i1 = __shfl_sync(0xffffffffu, inv, 4 + hsel);

    float4 z0, z1;
    z0.x = acc0.x * i0; z0.y = acc0.y * i0; z0.z = acc0.z * i0; z0.w = acc0.w * i0;
    z1.x = acc1.x * i1; z1.y = acc1.y * i1; z1.z = acc1.z * i1; z1.w = acc1.w * i1;
    z0.x = z0.x > 0.f ? z0.x : expm1f(z0.x);
    z0.y = z0.y > 0.f ? z0.y : expm1f(z0.y);
    z0.z = z0.z > 0.f ? z0.z : expm1f(z0.z);
    z0.w = z0.w > 0.f ? z0.w : expm1f(z0.w);
    z1.x = z1.x > 0.f ? z1.x : expm1f(z1.x);
    z1.y = z1.y > 0.f ? z1.y : expm1f(z1.y);
    z1.z = z1.z > 0.f ? z1.z : expm1f(z1.z);
    z1.w = z1.w > 0.f ? z1.w : expm1f(z1.w);

    float4* zp = (float4*)&g_z[(size_t)w * HD];
    zp[lane]      = z0;
    zp[32 + lane] = z1;
}

// -------- K6: out = zcat @ sem_w + sem_b. 128x128 tile, split-N micro, k-chunk 32 --------
__global__ void __launch_bounds__(256, 2)
k_gemm_out(const float* __restrict__ sw, const float* __restrict__ sb,
           float* __restrict__ out) {
    const int m0 = blockIdx.x * 128;

    __shared__ float As[32][132];
    __shared__ float Bs[32][128];

    const int tid = threadIdx.x;
    const int tx  = tid & 15;
    const int ty  = tid >> 4;
    float acc[8][8] = {};

    for (int kc = 0; kc < KTOT; kc += 32) {
        const int pch = kc >> 8;
        const int kk0 = kc & 255;
#pragma unroll
        for (int j = 0; j < 4; j++) {            // A: 128 rows x 32 k from g_z
            int t   = tid + j * 256;
            int row = t >> 3;
            int kg  = (t & 7) * 4;
            int gr  = m0 + row;
            float4 v = make_float4(0.f, 0.f, 0.f, 0.f);
            if (gr < NN)
                v = *(const float4*)&g_z[((size_t)pch * NN + gr) * HD + kk0 + kg];
            As[kg + 0][row] = v.x; As[kg + 1][row] = v.y;
            As[kg + 2][row] = v.z; As[kg + 3][row] = v.w;
        }
#pragma unroll
        for (int j = 0; j < 4; j++) {            // B: 32 k x 128 n
            int t = tid + j * 256;
            int k = t >> 5;
            int n = (t & 31) * 4;
            *(float4*)&Bs[k][n] = *(const float4*)&sw[(size_t)(kc + k) * EMB + n];
        }
        __syncthreads();
#pragma unroll
        for (int k = 0; k < 32; k++) {
            float4 a0 = *(float4*)&As[k][ty * 8];
            float4 a1 = *(float4*)&As[k][ty * 8 + 4];
            float4 b0 = *(float4*)&Bs[k][tx * 4];
            float4 b1 = *(float4*)&Bs[k][64 + tx * 4];
            float a[8] = {a0.x, a0.y, a0.z, a0.w, a1.x, a1.y, a1.z, a1.w};
            float b[8] = {b0.x, b0.y, b0.z, b0.w, b1.x, b1.y, b1.z, b1.w};
#pragma unroll
            for (int i = 0; i < 8; i++)
#pragma unroll
                for (int j2 = 0; j2 < 8; j2++) acc[i][j2] += a[i] * b[j2];
        }
        __syncthreads();
    }

    float bias0[4], bias1[4];
#pragma unroll
    for (int j = 0; j < 4; j++) {
        bias0[j] = sb[tx * 4 + j];
        bias1[j] = sb[64 + tx * 4 + j];
    }
#pragma unroll
    for (int i = 0; i < 8; i++) {
        int row = m0 + ty * 8 + i;
        if (row >= NN) continue;
        float4 v0 = make_float4(acc[i][0] + bias0[0], acc[i][1] + bias0[1],
                                acc[i][2] + bias0[2], acc[i][3] + bias0[3]);
        float4 v1 = make_float4(acc[i][4] + bias1[0], acc[i][5] + bias1[1],
                                acc[i][6] + bias1[2], acc[i][7] + bias1[3]);
        float* op = &out[(size_t)row * EMB + tx * 4];
        *(float4*)op        = v0;
        *(float4*)(op + 64) = v1;
    }
}

extern "C" void kernel_launch(void* const* d_in, const int* in_sizes, int n_in,
                              void* d_out, int out_size) {
    const float* h  = (const float*)d_in[0];
    const int*   ei = (const int*)  d_in[1];
    const float* fw = (const float*)d_in[2];
    const float* al = (const float*)d_in[3];
    const float* ar = (const float*)d_in[4];
    const float* sw = (const float*)d_in[5];
    const float* sb = (const float*)d_in[6];
    float* out = (float*)d_out;

    k_zero_deg<<<(M_ROWS + 255) / 256, 256>>>();                 // 1
    k_hist<<<(PP * EE + 255) / 256, 256>>>(ei);                  // 2
    k_scan1<<<NBLK_SCAN, 256>>>();                               // 3

    dim3 g1((NN + 127) / 128, HD / 128, PP);
    k_gemm_feat<<<g1, 256>>>(h, fw, al, ar);                     // 4 (profiled)

    k_scan23<<<(M_ROWS + 255) / 256, 256>>>();                   // 5
    k_scatter<<<(PP * EE + 255) / 256, 256>>>(ei);               // 6

    k_gather<<<(M_ROWS + 7) / 8, 256>>>();                       // 7

    k_gemm_out<<<(NN + 127) / 128, 256>>>(sw, sb, out);          // 8
}

// round 14
// speedup vs baseline: 1.6964x; 1.5917x over previous
#include <cuda_runtime.h>
#include <math_constants.h>

#define NN     50000
#define EE     800000
#define PP     3
#define INF_   128
#define HH     8
#define DD     32
#define HD     256
#define EMB    128
#define KTOT   768
#define M_ROWS (PP * NN)
#define NBLK_SCAN ((M_ROWS + 2047) / 2048)

// -------- device scratch --------
__device__ float g_feat[(size_t)PP * NN * HD];
__device__ float g_z   [(size_t)PP * NN * HD];
__device__ float g_el  [M_ROWS * HH];
__device__ float g_er  [M_ROWS * HH];
__device__ int   g_deg [M_ROWS];
__device__ int   g_off [M_ROWS];
__device__ int   g_cur [M_ROWS];
__device__ int   g_bsum[256];
__device__ int   g_csrc[PP * EE];

__device__ __forceinline__ float lrelu(float x) { return x > 0.f ? x : 0.2f * x; }

__device__ __forceinline__ unsigned f2tf32(float f) {
    unsigned u;
    asm("cvt.rna.tf32.f32 %0, %1;" : "=r"(u) : "f"(f));
    return u;
}

__device__ __forceinline__ void mma_tf32(float d[4], const unsigned a[4], const unsigned b[2]) {
    asm volatile(
        "mma.sync.aligned.m16n8k8.row.col.f32.tf32.tf32.f32 "
        "{%0,%1,%2,%3}, {%4,%5,%6,%7}, {%8,%9}, {%0,%1,%2,%3};"
        : "+f"(d[0]), "+f"(d[1]), "+f"(d[2]), "+f"(d[3])
        : "r"(a[0]), "r"(a[1]), "r"(a[2]), "r"(a[3]), "r"(b[0]), "r"(b[1]));
}

// -------- CSR build --------
__global__ void k_zero_deg() {
    int i = blockIdx.x * blockDim.x + threadIdx.x;
    if (i < M_ROWS) g_deg[i] = 0;
}

__global__ void k_hist(const int* __restrict__ ei) {
    int id = blockIdx.x * blockDim.x + threadIdx.x;
    if (id >= PP * EE) return;
    int p = id / EE, e = id - p * EE;
    int dst = ei[(size_t)p * 2 * EE + EE + e];
    atomicAdd(&g_deg[p * NN + dst], 1);
}

__global__ void k_scan1() {
    __shared__ int sd[256];
    int b = blockIdx.x, t = threadIdx.x;
    int base = b * 2048 + t * 8;
    int v[8]; int s = 0;
#pragma unroll
    for (int i = 0; i < 8; i++) {
        int x = (base + i < M_ROWS) ? g_deg[base + i] : 0;
        v[i] = s; s += x;
    }
    sd[t] = s; __syncthreads();
    for (int off = 1; off < 256; off <<= 1) {
        int x = (t >= off) ? sd[t - off] : 0;
        __syncthreads();
        sd[t] += x;
        __syncthreads();
    }
    int exc = sd[t] - s;
#pragma unroll
    for (int i = 0; i < 8; i++)
        if (base + i < M_ROWS) g_off[base + i] = exc + v[i];
    if (t == 255) g_bsum[b] = sd[255];
}

__global__ void k_scan23() {
    __shared__ int sb[NBLK_SCAN];
    if (threadIdx.x < NBLK_SCAN) sb[threadIdx.x] = g_bsum[threadIdx.x];
    __syncthreads();
    int i = blockIdx.x * blockDim.x + threadIdx.x;
    if (i >= M_ROWS) return;
    int b = i >> 11;
    int s = 0;
    for (int j = 0; j < b; j++) s += sb[j];
    int o = g_off[i] + s;
    g_off[i] = o;
    g_cur[i] = o;
}

__global__ void k_scatter(const int* __restrict__ ei) {
    int id = blockIdx.x * blockDim.x + threadIdx.x;
    if (id >= PP * EE) return;
    int p = id / EE, e = id - p * EE;
    int src = ei[(size_t)p * 2 * EE + e];
    int dst = ei[(size_t)p * 2 * EE + EE + e];
    int pos = atomicAdd(&g_cur[p * NN + dst], 1);
    g_csrc[pos] = src;
}

// -------- K1: feat = h @ fc_w (tf32 tensor core), fused el/er epilogue --------
// 128x128 tile, 8 warps each 32x64 (m16n8k8 atoms: 2 m-tiles x 8 n-tiles).
// Asm[m][k] stride 36 -> bank 4r+c bijective (conflict-free frag loads & stores).
// Bsm[k][n] stride 136 -> bank 8c+g bijective (conflict-free).
__global__ void __launch_bounds__(256, 2)
k_gemm_feat(const float* __restrict__ hmat, const float* __restrict__ fw,
            const float* __restrict__ al, const float* __restrict__ ar) {
    const int p  = blockIdx.z;
    const int m0 = blockIdx.x * 128;
    const int n0 = blockIdx.y * 128;
    const float* W = fw + (size_t)p * INF_ * HD;

    __shared__ unsigned Asm[128][36];
    __shared__ unsigned Bsm[32][136];

    const int tid  = threadIdx.x;
    const int lane = tid & 31;
    const int warp = tid >> 5;
    const int m0w  = (warp & 3) * 32;
    const int n0w  = (warp >> 2) * 64;
    const int r    = lane >> 2;
    const int c    = lane & 3;

    float acc[2][8][4];
#pragma unroll
    for (int mi = 0; mi < 2; mi++)
#pragma unroll
        for (int nj = 0; nj < 8; nj++)
#pragma unroll
            for (int q = 0; q < 4; q++) acc[mi][nj][q] = 0.f;

    for (int kc = 0; kc < INF_; kc += 32) {
#pragma unroll
        for (int j = 0; j < 4; j++) {              // A chunk: 128 rows x 32 k
            int t   = tid + j * 256;
            int row = t >> 3;
            int k4  = (t & 7) * 4;
            int gr  = m0 + row;
            float4 v = make_float4(0.f, 0.f, 0.f, 0.f);
            if (gr < NN) v = *(const float4*)&hmat[(size_t)gr * INF_ + kc + k4];
            uint4 u = make_uint4(f2tf32(v.x), f2tf32(v.y), f2tf32(v.z), f2tf32(v.w));
            *(uint4*)&Asm[row][k4] = u;
        }
#pragma unroll
        for (int j = 0; j < 4; j++) {              // B chunk: 32 k x 128 n
            int t = tid + j * 256;
            int k = t >> 5;
            int n = (t & 31) * 4;
            float4 v = *(const float4*)&W[(size_t)(kc + k) * HD + n0 + n];
            uint4 u = make_uint4(f2tf32(v.x), f2tf32(v.y), f2tf32(v.z), f2tf32(v.w));
            *(uint4*)&Bsm[k][n] = u;
        }
        __syncthreads();
#pragma unroll
        for (int ks = 0; ks < 4; ks++) {
            const int kk = ks * 8;
            unsigned a[2][4], b[8][2];
#pragma unroll
            for (int mi = 0; mi < 2; mi++) {
                int mr = m0w + mi * 16 + r;
                a[mi][0] = Asm[mr][kk + c];
                a[mi][1] = Asm[mr + 8][kk + c];
                a[mi][2] = Asm[mr][kk + c + 4];
                a[mi][3] = Asm[mr + 8][kk + c + 4];
            }
#pragma unroll
            for (int nj = 0; nj < 8; nj++) {
                int nc = n0w + nj * 8 + r;
                b[nj][0] = Bsm[kk + c][nc];
                b[nj][1] = Bsm[kk + c + 4][nc];
            }
#pragma unroll
            for (int mi = 0; mi < 2; mi++)
#pragma unroll
                for (int nj = 0; nj < 8; nj++)
                    mma_tf32(acc[mi][nj], a[mi], b[nj]);
        }
        __syncthreads();
    }

    // epilogue: feat stores + fused el/er
#pragma unroll
    for (int mi = 0; mi < 2; mi++) {
        int R0 = m0 + m0w + mi * 16 + r;
        int R1 = R0 + 8;
#pragma unroll
        for (int nj = 0; nj < 8; nj++) {
            int C = n0 + n0w + nj * 8 + 2 * c;
            if (R0 < NN)
                *(float2*)&g_feat[((size_t)p * NN + R0) * HD + C] =
                    make_float2(acc[mi][nj][0], acc[mi][nj][1]);
            if (R1 < NN)
                *(float2*)&g_feat[((size_t)p * NN + R1) * HD + C] =
                    make_float2(acc[mi][nj][2], acc[mi][nj][3]);
        }
#pragma unroll
        for (int hg = 0; hg < 2; hg++) {
            float el0 = 0.f, er0 = 0.f, el1 = 0.f, er1 = 0.f;
#pragma unroll
            for (int q = 0; q < 4; q++) {
                int nj = hg * 4 + q;
                int C  = n0 + n0w + nj * 8 + 2 * c;
                float2 av = *(const float2*)&al[p * HD + C];
                float2 rv = *(const float2*)&ar[p * HD + C];
                el0 += acc[mi][nj][0] * av.x + acc[mi][nj][1] * av.y;
                el1 += acc[mi][nj][2] * av.x + acc[mi][nj][3] * av.y;
                er0 += acc[mi][nj][0] * rv.x + acc[mi][nj][1] * rv.y;
                er1 += acc[mi][nj][2] * rv.x + acc[mi][nj][3] * rv.y;
            }
#pragma unroll
            for (int o = 1; o <= 2; o <<= 1) {
                el0 += __shfl_xor_sync(0xffffffffu, el0, o);
                el1 += __shfl_xor_sync(0xffffffffu, el1, o);
                er0 += __shfl_xor_sync(0xffffffffu, er0, o);
                er1 += __shfl_xor_sync(0xffffffffu, er1, o);
            }
            if (c == 0) {
                int head = ((n0 + n0w) >> 5) + hg;
                if (R0 < NN) {
                    g_el[(p * NN + R0) * HH + head] = el0;
                    g_er[(p * NN + R0) * HH + head] = er0;
                }
                if (R1 < NN) {
                    g_el[(p * NN + R1) * HH + head] = el1;
                    g_er[(p * NN + R1) * HH + head] = er1;
                }
            }
        }
    }
}

// -------- K3: single-pass softmax + aggregate + ELU, warp per (p,dst), unroll 4 --------
__global__ void k_gather() {
    int w    = (int)((blockIdx.x * (size_t)blockDim.x + threadIdx.x) >> 5);
    int lane = threadIdx.x & 31;
    if (w >= M_ROWS) return;
    int p   = w / NN;
    int beg = g_off[w];
    int end = beg + g_deg[w];

    float er_h = (lane < HH) ? g_er[w * HH + lane] : 0.f;

    float4 acc0 = make_float4(0.f, 0.f, 0.f, 0.f);
    float4 acc1 = make_float4(0.f, 0.f, 0.f, 0.f);
    float  den  = 0.f;
    const int hsel = lane >> 3;

    int i = beg;
    for (; i + 4 <= end; i += 4) {
        int s0 = g_csrc[i];
        int s1 = g_csrc[i + 1];
        int s2 = g_csrc[i + 2];
        int s3 = g_csrc[i + 3];
        const float4* f0 = (const float4*)&g_feat[(size_t)(p * NN + s0) * HD];
        const float4* f1 = (const float4*)&g_feat[(size_t)(p * NN + s1) * HD];
        const float4* f2 = (const float4*)&g_feat[(size_t)(p * NN + s2) * HD];
        const float4* f3 = (const float4*)&g_feat[(size_t)(p * NN + s3) * HD];
        float ex0 = 0.f, ex1 = 0.f, ex2 = 0.f, ex3 = 0.f;
        if (lane < HH) {
            float el0 = g_el[(p * NN + s0) * HH + lane];
            float el1 = g_el[(p * NN + s1) * HH + lane];
            float el2 = g_el[(p * NN + s2) * HH + lane];
            float el3 = g_el[(p * NN + s3) * HH + lane];
            ex0 = __expf(lrelu(el0 + er_h));
            ex1 = __expf(lrelu(el1 + er_h));
            ex2 = __expf(lrelu(el2 + er_h));
            ex3 = __expf(lrelu(el3 + er_h));
            den += (ex0 + ex1) + (ex2 + ex3);
        }
        float4 u0 = f0[lane],      u1 = f0[32 + lane];
        float4 v0 = f1[lane],      v1 = f1[32 + lane];
        float4 w0 = f2[lane],      w1 = f2[32 + lane];
        float4 x0 = f3[lane],      x1 = f3[32 + lane];
        float e00 = __shfl_sync(0xffffffffu, ex0, hsel);
        float e01 = __shfl_sync(0xffffffffu, ex0, 4 + hsel);
        float e10 = __shfl_sync(0xffffffffu, ex1, hsel);
        float e11 = __shfl_sync(0xffffffffu, ex1, 4 + hsel);
        float e20 = __shfl_sync(0xffffffffu, ex2, hsel);
        float e21 = __shfl_sync(0xffffffffu, ex2, 4 + hsel);
        float e30 = __shfl_sync(0xffffffffu, ex3, hsel);
        float e31 = __shfl_sync(0xffffffffu, ex3, 4 + hsel);
        acc0.x += u0.x * e00 + v0.x * e10 + w0.x * e20 + x0.x * e30;
        acc0.y += u0.y * e00 + v0.y * e10 + w0.y * e20 + x0.y * e30;
        acc0.z += u0.z * e00 + v0.z * e10 + w0.z * e20 + x0.z * e30;
        acc0.w += u0.w * e00 + v0.w * e10 + w0.w * e20 + x0.w * e30;
        acc1.x += u1.x * e01 + v1.x * e11 + w1.x * e21 + x1.x * e31;
        acc1.y += u1.y * e01 + v1.y * e11 + w1.y * e21 + x1.y * e31;
        acc1.z += u1.z * e01 + v1.z * e11 + w1.z * e21 + x1.z * e31;
        acc1.w += u1.w * e01 + v1.w * e11 + w1.w * e21 + x1.w * e31;
    }
    for (; i < end; i++) {
        int src = g_csrc[i];
        const float4* f = (const float4*)&g_feat[(size_t)(p * NN + src) * HD];
        float ex = 0.f;
        if (lane < HH) {
            float el = g_el[(p * NN + src) * HH + lane];
            ex = __expf(lrelu(el + er_h));
            den += ex;
        }
        float e0 = __shfl_sync(0xffffffffu, ex, hsel);
        float e1 = __shfl_sync(0xffffffffu, ex, 4 + hsel);
        float4 v0 = f[lane];
        float4 v1 = f[32 + lane];
        acc0.x += v0.x * e0; acc0.y += v0.y * e0;
        acc0.z += v0.z * e0; acc0.w += v0.w * e0;
        acc1.x += v1.x * e1; acc1.y += v1.y * e1;
        acc1.z += v1.z * e1; acc1.w += v1.w * e1;
    }

    float inv = 0.f;
    if (lane < HH) inv = (den > 0.f) ? 1.f / den : 0.f;
    float i0 = __shfl_sync(0xffffffffu, inv, hsel);
    float i1 = __shfl_sync(0xffffffffu, inv, 4 + hsel);

    float4 z0, z1;
    z0.x = acc0.x * i0; z0.y = acc0.y * i0; z0.z = acc0.z * i0; z0.w = acc0.w * i0;
    z1.x = acc1.x * i1; z1.y = acc1.y * i1; z1.z = acc1.z * i1; z1.w = acc1.w * i1;
    z0.x = z0.x > 0.f ? z0.x : expm1f(z0.x);
    z0.y = z0.y > 0.f ? z0.y : expm1f(z0.y);
    z0.z = z0.z > 0.f ? z0.z : expm1f(z0.z);
    z0.w = z0.w > 0.f ? z0.w : expm1f(z0.w);
    z1.x = z1.x > 0.f ? z1.x : expm1f(z1.x);
    z1.y = z1.y > 0.f ? z1.y : expm1f(z1.y);
    z1.z = z1.z > 0.f ? z1.z : expm1f(z1.z);
    z1.w = z1.w > 0.f ? z1.w : expm1f(z1.w);

    float4* zp = (float4*)&g_z[(size_t)w * HD];
    zp[lane]      = z0;
    zp[32 + lane] = z1;
}

// -------- K6: out = zcat @ sem_w + sem_b (tf32 tensor core), K=768 --------
__global__ void __launch_bounds__(256, 2)
k_gemm_out(const float* __restrict__ sw, const float* __restrict__ sb,
           float* __restrict__ out) {
    const int m0 = blockIdx.x * 128;

    __shared__ unsigned Asm[128][36];
    __shared__ unsigned Bsm[32][136];

    const int tid  = threadIdx.x;
    const int lane = tid & 31;
    const int warp = tid >> 5;
    const int m0w  = (warp & 3) * 32;
    const int n0w  = (warp >> 2) * 64;
    const int r    = lane >> 2;
    const int c    = lane & 3;

    float acc[2][8][4];
#pragma unroll
    for (int mi = 0; mi < 2; mi++)
#pragma unroll
        for (int nj = 0; nj < 8; nj++)
#pragma unroll
            for (int q = 0; q < 4; q++) acc[mi][nj][q] = 0.f;

    for (int kc = 0; kc < KTOT; kc += 32) {
        const int pch = kc >> 8;
        const int kk0 = kc & 255;
#pragma unroll
        for (int j = 0; j < 4; j++) {              // A chunk from g_z
            int t   = tid + j * 256;
            int row = t >> 3;
            int k4  = (t & 7) * 4;
            int gr  = m0 + row;
            float4 v = make_float4(0.f, 0.f, 0.f, 0.f);
            if (gr < NN)
                v = *(const float4*)&g_z[((size_t)pch * NN + gr) * HD + kk0 + k4];
            uint4 u = make_uint4(f2tf32(v.x), f2tf32(v.y), f2tf32(v.z), f2tf32(v.w));
            *(uint4*)&Asm[row][k4] = u;
        }
#pragma unroll
        for (int j = 0; j < 4; j++) {              // B chunk: 32 k x 128 n
            int t = tid + j * 256;
            int k = t >> 5;
            int n = (t & 31) * 4;
            float4 v = *(const float4*)&sw[(size_t)(kc + k) * EMB + n];
            uint4 u = make_uint4(f2tf32(v.x), f2tf32(v.y), f2tf32(v.z), f2tf32(v.w));
            *(uint4*)&Bsm[k][n] = u;
        }
        __syncthreads();
#pragma unroll
        for (int ks = 0; ks < 4; ks++) {
            const int kk = ks * 8;
            unsigned a[2][4], b[8][2];
#pragma unroll
            for (int mi = 0; mi < 2; mi++) {
                int mr = m0w + mi * 16 + r;
                a[mi][0] = Asm[mr][kk + c];
                a[mi][1] = Asm[mr + 8][kk + c];
                a[mi][2] = Asm[mr][kk + c + 4];
                a[mi][3] = Asm[mr + 8][kk + c + 4];
            }
#pragma unroll
            for (int nj = 0; nj < 8; nj++) {
                int nc = n0w + nj * 8 + r;
                b[nj][0] = Bsm[kk + c][nc];
                b[nj][1] = Bsm[kk + c + 4][nc];
            }
#pragma unroll
            for (int mi = 0; mi < 2; mi++)
#pragma unroll
                for (int nj = 0; nj < 8; nj++)
                    mma_tf32(acc[mi][nj], a[mi], b[nj]);
        }
        __syncthreads();
    }

#pragma unroll
    for (int mi = 0; mi < 2; mi++) {
        int R0 = m0 + m0w + mi * 16 + r;
        int R1 = R0 + 8;
#pragma unroll
        for (int nj = 0; nj < 8; nj++) {
            int C = n0w + nj * 8 + 2 * c;
            float2 bv = *(const float2*)&sb[C];
            if (R0 < NN)
                *(float2*)&out[(size_t)R0 * EMB + C] =
                    make_float2(acc[mi][nj][0] + bv.x, acc[mi][nj][1] + bv.y);
            if (R1 < NN)
                *(float2*)&out[(size_t)R1 * EMB + C] =
                    make_float2(acc[mi][nj][2] + bv.x, acc[mi][nj][3] + bv.y);
        }
    }
}

extern "C" void kernel_launch(void* const* d_in, const int* in_sizes, int n_in,
                              void* d_out, int out_size) {
    const float* h  = (const float*)d_in[0];
    const int*   ei = (const int*)  d_in[1];
    const float* fw = (const float*)d_in[2];
    const float* al = (const float*)d_in[3];
    const float* ar = (const float*)d_in[4];
    const float* sw = (const float*)d_in[5];
    const float* sb = (const float*)d_in[6];
    float* out = (float*)d_out;

    k_zero_deg<<<(M_ROWS + 255) / 256, 256>>>();                 // 1
    k_hist<<<(PP * EE + 255) / 256, 256>>>(ei);                  // 2
    k_scan1<<<NBLK_SCAN, 256>>>();                               // 3

    dim3 g1((NN + 127) / 128, HD / 128, PP);
    k_gemm_feat<<<g1, 256>>>(h, fw, al, ar);                     // 4 (profiled)

    k_scan23<<<(M_ROWS + 255) / 256, 256>>>();                   // 5
    k_scatter<<<(PP * EE + 255) / 256, 256>>>(ei);               // 6

    k_gather<<<(M_ROWS + 7) / 8, 256>>>();                       // 7

    k_gemm_out<<<(NN + 127) / 128, 256>>>(sw, sb, out);          // 8
}